// round 6
// baseline (speedup 1.0000x reference)
#include <cuda_runtime.h>
#include <cuda_bf16.h>
#include <math.h>

#define NN 50000
#define NF 128
#define DIM 10
#define NE 1600000
#define NG 1000
#define PD 12            // padded feature stride (10 -> 12, 3x float4)

// ---------------- scratch (no allocations allowed) ----------------
__device__ int    g_csr[NE];        // src ids grouped by dst
__device__ int    g_deg[NN];
__device__ int    g_row[NN + 1];    // CSR row starts
__device__ int    g_cur[NN];        // scatter cursors
__device__ float  g_deginv[NN];
__device__ float4 g_xl[NN * 3];
__device__ float4 g_xr[NN * 3];
__device__ float4 g_hl[NN * 3];
__device__ float4 g_hr[NN * 3];
__device__ float  g_pool[NG * PD];
__device__ int    g_cnt[NG];
__device__ int    g_ei32;   // 1 if edge_index arrived as int32
__device__ int    g_b32;    // 1 if batch arrived as int32

__device__ __forceinline__ void redf(float* p, float v) {
    asm volatile("red.global.add.f32 [%0], %1;" :: "l"(p), "f"(v) : "memory");
}

// ---------------- kernels ----------------
__global__ void init_k(const long long* ei, const long long* batch) {
    int i = blockIdx.x * blockDim.x + threadIdx.x;
    int stride = gridDim.x * blockDim.x;
    for (int j = i; j < NN; j += stride) g_deg[j] = 0;
    for (int j = i; j < NG * PD; j += stride) g_pool[j] = 0.f;
    for (int j = i; j < NG; j += stride) g_cnt[j] = 0;
    if (i == 0) {
        int f = 0;
        for (int k = 0; k < 64; k++) {
            long long v = ei[k];
            if (v < 0 || v >= NN) f = 1;
        }
        g_ei32 = f;
        int fb = 0;
        for (int k = 0; k < 64; k++) {
            long long v = batch[12000 + k];
            if (v < 0 || v >= NG) fb = 1;
        }
        g_b32 = fb;
    }
}

// Count in-degree; 4 edges per thread for MLP on the atomics.
__global__ void deg_count(const long long* __restrict__ ei) {
    int t = blockIdx.x * blockDim.x + threadIdx.x;
    int e0 = t * 4;
    if (e0 >= NE) return;
    int d[4]; int m = min(4, NE - e0);
    if (g_ei32) {
        const int* e32 = (const int*)ei;
#pragma unroll
        for (int i = 0; i < 4; i++) if (i < m) d[i] = e32[NE + e0 + i];
    } else {
#pragma unroll
        for (int i = 0; i < 4; i++) if (i < m) d[i] = (int)ei[NE + e0 + i];
    }
#pragma unroll
    for (int i = 0; i < 4; i++)
        if (i < m) atomicAdd(&g_deg[d[i]], 1);
}

// Single-block exclusive scan of deg -> row starts + cursors + deginv.
__global__ __launch_bounds__(1024) void scan_deg() {
    __shared__ int sh[1024];
    int t = threadIdx.x;
    const int PER = (NN + 1023) / 1024;   // 49
    int base = t * PER;
    int sum = 0;
    for (int i = 0; i < PER; i++) {
        int idx = base + i;
        if (idx < NN) sum += g_deg[idx];
    }
    sh[t] = sum;
    __syncthreads();
    for (int off = 1; off < 1024; off <<= 1) {
        int v = (t >= off) ? sh[t - off] : 0;
        __syncthreads();
        sh[t] += v;
        __syncthreads();
    }
    int running = sh[t] - sum;   // exclusive prefix
    for (int i = 0; i < PER; i++) {
        int idx = base + i;
        if (idx < NN) {
            g_row[idx] = running;
            g_cur[idx] = running;
            int dg = g_deg[idx];
            g_deginv[idx] = 1.0f / fmaxf((float)dg, 1.0f);
            running += dg;
        }
    }
    if (t == 0) g_row[NN] = NE;
}

// Counting-sort scatter: group src ids by destination; 4 edges/thread.
__global__ void scatter_csr(const long long* __restrict__ ei) {
    int t = blockIdx.x * blockDim.x + threadIdx.x;
    int e0 = t * 4;
    if (e0 >= NE) return;
    int m = min(4, NE - e0);
    int s[4], d[4];
    if (g_ei32) {
        const int* e32 = (const int*)ei;
#pragma unroll
        for (int i = 0; i < 4; i++) if (i < m) { s[i] = e32[e0 + i]; d[i] = e32[NE + e0 + i]; }
    } else {
#pragma unroll
        for (int i = 0; i < 4; i++) if (i < m) { s[i] = (int)ei[e0 + i]; d[i] = (int)ei[NE + e0 + i]; }
    }
    int pos[4];
#pragma unroll
    for (int i = 0; i < 4; i++) if (i < m) pos[i] = atomicAdd(&g_cur[d[i]], 1);
#pragma unroll
    for (int i = 0; i < 4; i++) if (i < m) g_csr[pos[i]] = s[i];
}

// Fused GEMV: xl = x @ W1_l^T, xr = x @ W1_r^T
__global__ __launch_bounds__(256) void gemv1(const float* __restrict__ x,
                                             const float* __restrict__ W1l,
                                             const float* __restrict__ W1r) {
    __shared__ __align__(16) float sW[20 * 128];
    __shared__ __align__(16) float sX[64 * 132];
    int t = threadIdx.x;
    for (int i = t; i < 20 * 128; i += 256) {
        int d = i >> 7, k = i & 127;
        sW[i] = (d < 10) ? W1l[d * 128 + k] : W1r[(d - 10) * 128 + k];
    }
    int n0 = blockIdx.x * 64;
    for (int i = t; i < 64 * 32; i += 256) {
        int n = i >> 5, k4 = i & 31;
        int node = n0 + n;
        float4 v = (node < NN) ? ((const float4*)x)[node * 32 + k4]
                               : make_float4(0.f, 0.f, 0.f, 0.f);
        *(float4*)&sX[n * 132 + k4 * 4] = v;
    }
    __syncthreads();
    int n = t & 63, g = t >> 6;
    int node = n0 + n;
    float acc[5] = {0.f, 0.f, 0.f, 0.f, 0.f};
    const float4* xr4 = (const float4*)&sX[n * 132];
    const float4* w4  = (const float4*)sW;
#pragma unroll
    for (int k4 = 0; k4 < 32; k4++) {
        float4 xv = xr4[k4];
#pragma unroll
        for (int j = 0; j < 5; j++) {
            float4 w = w4[(g * 5 + j) * 32 + k4];
            acc[j] += xv.x * w.x + xv.y * w.y + xv.z * w.z + xv.w * w.w;
        }
    }
    if (node < NN) {
#pragma unroll
        for (int j = 0; j < 5; j++) {
            int d = g * 5 + j;
            float* dst = (d < 10) ? (float*)g_xl : (float*)g_xr;
            int dd = (d < 10) ? d : d - 10;
            dst[node * PD + dd] = acc[j];
        }
    }
}

// Warp-per-node segment sum: lanes gather edges in parallel, butterfly-reduce
// 12 accumulators, then lanes 0-9 / 16-25 compute the two 10x10 GEMV rows.
__global__ __launch_bounds__(256) void agg1_combine(const float* __restrict__ W2l,
                                                    const float* __restrict__ W2r) {
    __shared__ float sWl[112], sWr[112];
    int t = threadIdx.x;
    if (t < 100) { sWl[t] = W2l[t]; sWr[t] = W2r[t]; }
    __syncthreads();
    int n = (blockIdx.x * blockDim.x + t) >> 5;
    int lane = t & 31;
    if (n >= NN) return;
    int b0 = g_row[n], b1 = g_row[n + 1];
    float a[12];
#pragma unroll
    for (int j = 0; j < 12; j++) a[j] = 0.f;
    for (int e = b0 + lane; e < b1; e += 32) {
        int s = g_csr[e];
        const float4* f = &g_xl[s * 3];
        float4 p0 = f[0], p1 = f[1], p2 = f[2];
        a[0] += p0.x; a[1] += p0.y; a[2]  += p0.z; a[3]  += p0.w;
        a[4] += p1.x; a[5] += p1.y; a[6]  += p1.z; a[7]  += p1.w;
        a[8] += p2.x; a[9] += p2.y; a[10] += p2.z; a[11] += p2.w;
    }
#pragma unroll
    for (int m = 16; m >= 1; m >>= 1)
#pragma unroll
        for (int j = 0; j < 10; j++)        // dims 10,11 are padding: skip
            a[j] += __shfl_xor_sync(0xffffffffu, a[j], m);
    // every lane now holds full agg[0..9]
    float di = g_deginv[n];
    const float* xr = (const float*)g_xr + n * PD;
    float h[10];
#pragma unroll
    for (int j = 0; j < 10; j++) h[j] = fmaxf(a[j] * di + xr[j], 0.f);
    // lanes 0..11 -> hl row, lanes 16..27 -> hr row (rows 10,11 are zero pad)
    int r = lane & 15;
    if (r < 12) {
        float v = 0.f;
        if (r < 10) {
            const float* Wrow = (lane < 16) ? &sWl[r * 10] : &sWr[r * 10];
#pragma unroll
            for (int j = 0; j < 10; j++) v += Wrow[j] * h[j];
        }
        float* dst = (lane < 16) ? (float*)g_hl : (float*)g_hr;
        dst[n * PD + r] = v;
    }
}

// Layer 2 + global mean pool.
__global__ __launch_bounds__(256) void agg2_pool(const long long* __restrict__ batch) {
    int t = threadIdx.x;
    int n = (blockIdx.x * blockDim.x + t) >> 5;
    int lane = t & 31;
    if (n >= NN) return;
    int b0 = g_row[n], b1 = g_row[n + 1];
    float a[12];
#pragma unroll
    for (int j = 0; j < 12; j++) a[j] = 0.f;
    for (int e = b0 + lane; e < b1; e += 32) {
        int s = g_csr[e];
        const float4* f = &g_hl[s * 3];
        float4 p0 = f[0], p1 = f[1], p2 = f[2];
        a[0] += p0.x; a[1] += p0.y; a[2]  += p0.z; a[3]  += p0.w;
        a[4] += p1.x; a[5] += p1.y; a[6]  += p1.z; a[7]  += p1.w;
        a[8] += p2.x; a[9] += p2.y; a[10] += p2.z; a[11] += p2.w;
    }
#pragma unroll
    for (int m = 16; m >= 1; m >>= 1)
#pragma unroll
        for (int j = 0; j < 10; j++)
            a[j] += __shfl_xor_sync(0xffffffffu, a[j], m);
    float di = g_deginv[n];
    int b = g_b32 ? ((const int*)batch)[n] : (int)batch[n];
    if (lane < 10) {
        const float* hr = (const float*)g_hr + n * PD;
        float h2 = a[lane] * di + hr[lane];
        redf(&g_pool[b * PD + lane], h2);
    } else if (lane == 10) {
        atomicAdd(&g_cnt[b], 1);
    }
}

__global__ void final_out(const float* __restrict__ Wfc, float* __restrict__ out) {
    int g = blockIdx.x * blockDim.x + threadIdx.x;
    if (g >= NG) return;
    float c = fmaxf((float)g_cnt[g], 1.0f);
    const float* p = &g_pool[g * PD];
    float z = 0.f;
#pragma unroll
    for (int d = 0; d < 10; d++) z += p[d] * Wfc[d];
    z /= c;
    out[g] = 1.0f / (1.0f + expf(-z));
}

// ---------------- launch ----------------
extern "C" void kernel_launch(void* const* d_in, const int* in_sizes, int n_in,
                              void* d_out, int out_size) {
    const float *x = 0, *W1l = 0, *W1r = 0, *W2l = 0, *W2r = 0, *Wfc = 0;
    const long long *ei = 0, *batch = 0;
    for (int i = 0; i < n_in; i++) {
        int sz = in_sizes[i];
        if (sz == NN * NF)        x = (const float*)d_in[i];
        else if (sz == DIM * NF)  { if (!W1l) W1l = (const float*)d_in[i]; else W1r = (const float*)d_in[i]; }
        else if (sz == DIM * DIM) { if (!W2l) W2l = (const float*)d_in[i]; else W2r = (const float*)d_in[i]; }
        else if (sz == DIM)       Wfc = (const float*)d_in[i];
        else if (sz == 2 * NE)    ei = (const long long*)d_in[i];
        else if (sz == NN)        batch = (const long long*)d_in[i];
    }
    float* out = (float*)d_out;

    const int TB = 256;
    const int EB = (NE / 4 + TB - 1) / TB;       // 4 edges per thread
    const int WB = (NN * 32 + TB - 1) / TB;      // warp per node
    init_k<<<32, TB>>>(ei, batch);
    deg_count<<<EB, TB>>>(ei);
    scan_deg<<<1, 1024>>>();
    scatter_csr<<<EB, TB>>>(ei);
    gemv1<<<(NN + 63) / 64, TB>>>(x, W1l, W1r);
    agg1_combine<<<WB, TB>>>(W2l, W2r);
    agg2_pool<<<WB, TB>>>(batch);
    final_out<<<(NG + TB - 1) / TB, TB>>>(Wfc, out);
}

// round 7
// speedup vs baseline: 2.0587x; 2.0587x over previous
#include <cuda_runtime.h>
#include <cuda_fp16.h>
#include <math.h>

#define NN 50000
#define NF 128
#define DIM 10
#define NE 1600000
#define NG 1000
#define PD 12            // fp32 padded stride (10 -> 12, 3x float4)

// ---------------- scratch ----------------
__device__ int2   g_edge[NE];       // (src, dst)
__device__ int    g_deg[NN];
__device__ float  g_deginv[NN];
__device__ float4 g_xlh[NN * 2];    // xl rows as fp16: 16 halfs (10 used, pads 0)
__device__ float4 g_hlh[NN * 2];    // hl rows as fp16
__device__ float4 g_xr[NN * 3];     // fp32, PD=12
__device__ float4 g_hr[NN * 3];
__device__ float4 g_agg1[NN * 3];
__device__ float4 g_agg2[NN * 3];
__device__ float4 g_pool[NG * 3];
__device__ int    g_cnt[NG];
__device__ int    g_ei32;
__device__ int    g_b32;

__device__ __forceinline__ void red4(float4* p, float4 v) {
    asm volatile("red.global.add.v4.f32 [%0], {%1,%2,%3,%4};"
                 :: "l"(p), "f"(v.x), "f"(v.y), "f"(v.z), "f"(v.w) : "memory");
}

// ---------------- kernels ----------------
// Zero all accumulators + fp16 pads; thread 0 does dtype detection.
__global__ void init_k(const long long* ei, const long long* batch) {
    int i = blockIdx.x * blockDim.x + threadIdx.x;
    int stride = gridDim.x * blockDim.x;
    float4 z = make_float4(0.f, 0.f, 0.f, 0.f);
    for (int j = i; j < NN * 3; j += stride) { g_agg1[j] = z; g_agg2[j] = z; }
    for (int j = i; j < NN * 2; j += stride) { g_xlh[j] = z; g_hlh[j] = z; }
    for (int j = i; j < NG * 3; j += stride) g_pool[j] = z;
    for (int j = i; j < NN; j += stride) g_deg[j] = 0;
    for (int j = i; j < NG; j += stride) g_cnt[j] = 0;
    if (i == 0) {
        int f = 0;
        for (int k = 0; k < 64; k++) {
            long long v = ei[k];
            if (v < 0 || v >= NN) f = 1;
        }
        g_ei32 = f;
        int fb = 0;
        for (int k = 0; k < 64; k++) {
            long long v = batch[12000 + k];
            if (v < 0 || v >= NG) fb = 1;
        }
        g_b32 = fb;
    }
}

// Pack edges as int2 + count in-degree.
__global__ void prep_edges(const long long* __restrict__ ei) {
    int e = blockIdx.x * blockDim.x + threadIdx.x;
    if (e >= NE) return;
    int s, d;
    if (g_ei32) {
        const int* e32 = (const int*)ei;
        s = e32[e]; d = e32[NE + e];
    } else {
        s = (int)ei[e]; d = (int)ei[NE + e];
    }
    g_edge[e] = make_int2(s, d);
    atomicAdd(&g_deg[d], 1);
}

// Fused: xl = x@W1l^T (fp16), xr = x@W1r^T (fp32) + deg_inv + graph counts.
__global__ __launch_bounds__(256) void gemv1(const float* __restrict__ x,
                                             const float* __restrict__ W1l,
                                             const float* __restrict__ W1r,
                                             const long long* __restrict__ batch) {
    __shared__ __align__(16) float sW[20 * 128];
    __shared__ __align__(16) float sX[64 * 132];
    int t = threadIdx.x;
    for (int i = t; i < 20 * 128; i += 256) {
        int d = i >> 7, k = i & 127;
        sW[i] = (d < 10) ? W1l[d * 128 + k] : W1r[(d - 10) * 128 + k];
    }
    int n0 = blockIdx.x * 64;
    for (int i = t; i < 64 * 32; i += 256) {
        int n = i >> 5, k4 = i & 31;
        int node = n0 + n;
        float4 v = (node < NN) ? ((const float4*)x)[node * 32 + k4]
                               : make_float4(0.f, 0.f, 0.f, 0.f);
        *(float4*)&sX[n * 132 + k4 * 4] = v;
    }
    __syncthreads();
    int n = t & 63, g = t >> 6;
    int node = n0 + n;
    float acc[5] = {0.f, 0.f, 0.f, 0.f, 0.f};
    const float4* xr4 = (const float4*)&sX[n * 132];
    const float4* w4  = (const float4*)sW;
#pragma unroll
    for (int k4 = 0; k4 < 32; k4++) {
        float4 xv = xr4[k4];
#pragma unroll
        for (int j = 0; j < 5; j++) {
            float4 w = w4[(g * 5 + j) * 32 + k4];
            acc[j] += xv.x * w.x + xv.y * w.y + xv.z * w.z + xv.w * w.w;
        }
    }
    if (node < NN) {
        __half* xlh = (__half*)g_xlh;
#pragma unroll
        for (int j = 0; j < 5; j++) {
            int d = g * 5 + j;
            if (d < 10) xlh[node * 16 + d] = __float2half(acc[j]);
            else        ((float*)g_xr)[node * PD + (d - 10)] = acc[j];
        }
        if (g == 0) {   // one thread per node: deg_inv + graph count
            g_deginv[node] = 1.0f / fmaxf((float)g_deg[node], 1.0f);
            int b = g_b32 ? ((const int*)batch)[node] : (int)batch[node];
            atomicAdd(&g_cnt[b], 1);
        }
    }
}

// Edge pass: gather fp16 row (2x LDG.128 = one 32B sector pair), convert,
// vector-reduce fp32 into agg. PASS 0: xlh->agg1, PASS 1: hlh->agg2.
template<int PASS>
__global__ __launch_bounds__(256) void edge_agg() {
    const float4* __restrict__ feat = (PASS == 0) ? g_xlh : g_hlh;
    float4* agg                     = (PASS == 0) ? g_agg1 : g_agg2;
    int e = blockIdx.x * blockDim.x + threadIdx.x;
    if (e >= NE) return;
    int2 sd = g_edge[e];
    float4 u0 = feat[sd.x * 2 + 0];
    float4 u1 = feat[sd.x * 2 + 1];
    float2 f0 = __half22float2(*(__half2*)&u0.x);
    float2 f1 = __half22float2(*(__half2*)&u0.y);
    float2 f2 = __half22float2(*(__half2*)&u0.z);
    float2 f3 = __half22float2(*(__half2*)&u0.w);
    float2 f4 = __half22float2(*(__half2*)&u1.x);
    float4* base = &agg[sd.y * 3];
    red4(base + 0, make_float4(f0.x, f0.y, f1.x, f1.y));
    red4(base + 1, make_float4(f2.x, f2.y, f3.x, f3.y));
    red4(base + 2, make_float4(f4.x, f4.y, 0.f, 0.f));
}

// h1 = relu(agg1*deg_inv + xr); hl(fp16) = h1@W2l^T; hr(fp32) = h1@W2r^T
__global__ __launch_bounds__(256) void combine1(const float* __restrict__ W2l,
                                                const float* __restrict__ W2r) {
    __shared__ float sWl[100], sWr[100];
    int t = threadIdx.x;
    if (t < 100) { sWl[t] = W2l[t]; sWr[t] = W2r[t]; }
    __syncthreads();
    int n = blockIdx.x * blockDim.x + t;
    if (n >= NN) return;
    float di = g_deginv[n];
    const float* ag = (const float*)g_agg1 + n * PD;
    const float* xr = (const float*)g_xr + n * PD;
    float h[10];
#pragma unroll
    for (int d = 0; d < 10; d++) h[d] = fmaxf(ag[d] * di + xr[d], 0.f);
    __half* hlh = (__half*)g_hlh;
    float hr[12];
#pragma unroll
    for (int d = 0; d < 10; d++) {
        float al = 0.f, ar = 0.f;
#pragma unroll
        for (int j = 0; j < 10; j++) {
            al += sWl[d * 10 + j] * h[j];
            ar += sWr[d * 10 + j] * h[j];
        }
        hlh[n * 16 + d] = __float2half(al);
        hr[d] = ar;
    }
    hr[10] = hr[11] = 0.f;
    float4* pr = &g_hr[n * 3];
#pragma unroll
    for (int q = 0; q < 3; q++)
        pr[q] = make_float4(hr[q*4], hr[q*4+1], hr[q*4+2], hr[q*4+3]);
}

// h2 = agg2*deg_inv + hr; pool[batch[n]] += h2
__global__ __launch_bounds__(256) void combine2_pool(const long long* __restrict__ batch) {
    int n = blockIdx.x * blockDim.x + threadIdx.x;
    if (n >= NN) return;
    float di = g_deginv[n];
    const float* ag = (const float*)g_agg2 + n * PD;
    const float* hr = (const float*)g_hr + n * PD;
    float h2[12];
#pragma unroll
    for (int d = 0; d < 10; d++) h2[d] = ag[d] * di + hr[d];
    h2[10] = h2[11] = 0.f;
    int b = g_b32 ? ((const int*)batch)[n] : (int)batch[n];
    float4* pp = &g_pool[b * 3];
#pragma unroll
    for (int q = 0; q < 3; q++)
        red4(&pp[q], make_float4(h2[q*4], h2[q*4+1], h2[q*4+2], h2[q*4+3]));
}

__global__ void final_out(const float* __restrict__ Wfc, float* __restrict__ out) {
    int g = blockIdx.x * blockDim.x + threadIdx.x;
    if (g >= NG) return;
    float c = fmaxf((float)g_cnt[g], 1.0f);
    const float* p = (const float*)g_pool + g * PD;
    float z = 0.f;
#pragma unroll
    for (int d = 0; d < 10; d++) z += p[d] * Wfc[d];
    z /= c;
    out[g] = 1.0f / (1.0f + expf(-z));
}

// ---------------- launch ----------------
extern "C" void kernel_launch(void* const* d_in, const int* in_sizes, int n_in,
                              void* d_out, int out_size) {
    const float *x = 0, *W1l = 0, *W1r = 0, *W2l = 0, *W2r = 0, *Wfc = 0;
    const long long *ei = 0, *batch = 0;
    for (int i = 0; i < n_in; i++) {
        int sz = in_sizes[i];
        if (sz == NN * NF)        x = (const float*)d_in[i];
        else if (sz == DIM * NF)  { if (!W1l) W1l = (const float*)d_in[i]; else W1r = (const float*)d_in[i]; }
        else if (sz == DIM * DIM) { if (!W2l) W2l = (const float*)d_in[i]; else W2r = (const float*)d_in[i]; }
        else if (sz == DIM)       Wfc = (const float*)d_in[i];
        else if (sz == 2 * NE)    ei = (const long long*)d_in[i];
        else if (sz == NN)        batch = (const long long*)d_in[i];
    }
    float* out = (float*)d_out;

    const int TB = 256;
    init_k<<<512, TB>>>(ei, batch);
    prep_edges<<<(NE + TB - 1) / TB, TB>>>(ei);
    gemv1<<<(NN + 63) / 64, TB>>>(x, W1l, W1r, batch);
    edge_agg<0><<<(NE + TB - 1) / TB, TB>>>();
    combine1<<<(NN + TB - 1) / TB, TB>>>(W2l, W2r);
    edge_agg<1><<<(NE + TB - 1) / TB, TB>>>();
    combine2_pool<<<(NN + TB - 1) / TB, TB>>>(batch);
    final_out<<<(NG + TB - 1) / TB, TB>>>(Wfc, out);
}

// round 8
// speedup vs baseline: 2.4970x; 1.2129x over previous
#include <cuda_runtime.h>
#include <cuda_fp16.h>
#include <math.h>

#define NN 50000
#define NF 128
#define DIM 10
#define NE 1600000
#define NG 1000
#define PD 12            // fp32 padded stride (10 -> 12, 3x float4)

// ---------------- scratch ----------------
__device__ int2   g_edge[NE];       // (src, dst) packed once, reused in pass 2
__device__ int    g_deg[NN];
__device__ float  g_deginv[NN];
__device__ float4 g_xlh[NN * 2];    // xl rows fp16: 16 halfs (10 used, pads 0)
__device__ float4 g_hlh[NN * 2];    // hl rows fp16
__device__ float4 g_agg1h[NN * 2];  // fp16 accumulators (atomic f16x2 adds)
__device__ float4 g_agg2h[NN * 2];
__device__ float4 g_xr[NN * 3];     // fp32
__device__ float4 g_hr[NN * 3];
__device__ float4 g_pool[NG * 3];
__device__ int    g_cnt[NG];
__device__ int    g_ei32;
__device__ int    g_b32;

__device__ __forceinline__ void red4f(float4* p, float4 v) {
    asm volatile("red.global.add.v4.f32 [%0], {%1,%2,%3,%4};"
                 :: "l"(p), "f"(v.x), "f"(v.y), "f"(v.z), "f"(v.w) : "memory");
}
__device__ __forceinline__ void redh8(void* p, uint4 v) {      // 8 halfs
    asm volatile("red.global.add.noftz.v4.f16x2 [%0], {%1,%2,%3,%4};"
                 :: "l"(p), "r"(v.x), "r"(v.y), "r"(v.z), "r"(v.w) : "memory");
}
__device__ __forceinline__ void redh4(void* p, uint2 v) {      // 4 halfs
    asm volatile("red.global.add.noftz.v2.f16x2 [%0], {%1,%2};"
                 :: "l"(p), "r"(v.x), "r"(v.y) : "memory");
}

// ---------------- kernels ----------------
__global__ void init_k(const long long* ei, const long long* batch) {
    int i = blockIdx.x * blockDim.x + threadIdx.x;
    int stride = gridDim.x * blockDim.x;
    float4 z = make_float4(0.f, 0.f, 0.f, 0.f);
    for (int j = i; j < NN * 2; j += stride) {
        g_agg1h[j] = z; g_agg2h[j] = z; g_xlh[j] = z; g_hlh[j] = z;
    }
    for (int j = i; j < NG * 3; j += stride) g_pool[j] = z;
    for (int j = i; j < NN; j += stride) g_deg[j] = 0;
    for (int j = i; j < NG; j += stride) g_cnt[j] = 0;
    if (i == 0) {
        int f = 0;
        for (int k = 0; k < 64; k++) {
            long long v = ei[k];
            if (v < 0 || v >= NN) f = 1;
        }
        g_ei32 = f;
        int fb = 0;
        for (int k = 0; k < 64; k++) {
            long long v = batch[12000 + k];
            if (v < 0 || v >= NG) fb = 1;
        }
        g_b32 = fb;
    }
}

// Fused GEMV: xl = x@W1l^T (fp16 halves into g_xlh), xr = x@W1r^T (fp32).
__global__ __launch_bounds__(256) void gemv1(const float* __restrict__ x,
                                             const float* __restrict__ W1l,
                                             const float* __restrict__ W1r) {
    __shared__ __align__(16) float sW[20 * 128];
    __shared__ __align__(16) float sX[64 * 132];
    int t = threadIdx.x;
    for (int i = t; i < 20 * 128; i += 256) {
        int d = i >> 7, k = i & 127;
        sW[i] = (d < 10) ? W1l[d * 128 + k] : W1r[(d - 10) * 128 + k];
    }
    int n0 = blockIdx.x * 64;
    for (int i = t; i < 64 * 32; i += 256) {
        int n = i >> 5, k4 = i & 31;
        int node = n0 + n;
        float4 v = (node < NN) ? ((const float4*)x)[node * 32 + k4]
                               : make_float4(0.f, 0.f, 0.f, 0.f);
        *(float4*)&sX[n * 132 + k4 * 4] = v;
    }
    __syncthreads();
    int n = t & 63, g = t >> 6;
    int node = n0 + n;
    float acc[5] = {0.f, 0.f, 0.f, 0.f, 0.f};
    const float4* xr4 = (const float4*)&sX[n * 132];
    const float4* w4  = (const float4*)sW;
#pragma unroll
    for (int k4 = 0; k4 < 32; k4++) {
        float4 xv = xr4[k4];
#pragma unroll
        for (int j = 0; j < 5; j++) {
            float4 w = w4[(g * 5 + j) * 32 + k4];
            acc[j] += xv.x * w.x + xv.y * w.y + xv.z * w.z + xv.w * w.w;
        }
    }
    if (node < NN) {
        __half* xlh = (__half*)g_xlh;
#pragma unroll
        for (int j = 0; j < 5; j++) {
            int d = g * 5 + j;
            if (d < 10) xlh[node * 16 + d] = __float2half(acc[j]);
            else        ((float*)g_xr)[node * PD + (d - 10)] = acc[j];
        }
    }
}

// Edge pass. PASS 0: reads edge_index, packs g_edge, counts deg, RED xlh->agg1h.
//            PASS 1: reads g_edge, RED hlh->agg2h.
// 2 fp16 vector RED transactions per edge (vs 3 fp32) — LTS RMW bound.
template<int PASS>
__global__ __launch_bounds__(256) void edge_agg(const long long* __restrict__ ei) {
    int e = blockIdx.x * blockDim.x + threadIdx.x;
    if (e >= NE) return;
    int s, d;
    if (PASS == 0) {
        if (g_ei32) {
            const int* e32 = (const int*)ei;
            s = e32[e]; d = e32[NE + e];
        } else {
            s = (int)ei[e]; d = (int)ei[NE + e];
        }
        g_edge[e] = make_int2(s, d);
        atomicAdd(&g_deg[d], 1);
    } else {
        int2 sd = g_edge[e];
        s = sd.x; d = sd.y;
    }
    const uint4* feat = (PASS == 0) ? (const uint4*)g_xlh : (const uint4*)g_hlh;
    uint4 u0 = feat[s * 2 + 0];
    uint2 u1 = *(const uint2*)&feat[s * 2 + 1];   // halfs 8..11 (10,11 are zero)
    char* row = (char*)((PASS == 0) ? g_agg1h : g_agg2h) + (size_t)d * 32;
    redh8(row, u0);
    redh4(row + 16, u1);
}

// h1 = relu(agg1*deg_inv + xr); hl(fp16)=h1@W2l^T; hr(fp32)=h1@W2r^T; store deginv.
__global__ __launch_bounds__(256) void combine1(const float* __restrict__ W2l,
                                                const float* __restrict__ W2r) {
    __shared__ float sWl[100], sWr[100];
    int t = threadIdx.x;
    if (t < 100) { sWl[t] = W2l[t]; sWr[t] = W2r[t]; }
    __syncthreads();
    int n = blockIdx.x * blockDim.x + t;
    if (n >= NN) return;
    float di = 1.0f / fmaxf((float)g_deg[n], 1.0f);
    g_deginv[n] = di;
    uint4 a0 = *((const uint4*)g_agg1h + n * 2);
    uint2 a1 = *(const uint2*)((const uint4*)g_agg1h + n * 2 + 1);
    float ag[10];
    {
        float2 p;
        p = __half22float2(*(__half2*)&a0.x); ag[0] = p.x; ag[1] = p.y;
        p = __half22float2(*(__half2*)&a0.y); ag[2] = p.x; ag[3] = p.y;
        p = __half22float2(*(__half2*)&a0.z); ag[4] = p.x; ag[5] = p.y;
        p = __half22float2(*(__half2*)&a0.w); ag[6] = p.x; ag[7] = p.y;
        p = __half22float2(*(__half2*)&a1.x); ag[8] = p.x; ag[9] = p.y;
    }
    const float* xr = (const float*)g_xr + n * PD;
    float h[10];
#pragma unroll
    for (int d = 0; d < 10; d++) h[d] = fmaxf(ag[d] * di + xr[d], 0.f);
    __half hl16[16];
    float hr[12];
#pragma unroll
    for (int d = 0; d < 10; d++) {
        float al = 0.f, ar = 0.f;
#pragma unroll
        for (int j = 0; j < 10; j++) {
            al += sWl[d * 10 + j] * h[j];
            ar += sWr[d * 10 + j] * h[j];
        }
        hl16[d] = __float2half(al);
        hr[d] = ar;
    }
#pragma unroll
    for (int d = 10; d < 16; d++) hl16[d] = __float2half(0.f);
    // vector store full fp16 row (pads included)
    float4* dst = &g_hlh[n * 2];
    dst[0] = *(float4*)&hl16[0];
    dst[1] = *(float4*)&hl16[8];
    hr[10] = hr[11] = 0.f;
    float4* pr = &g_hr[n * 3];
#pragma unroll
    for (int q = 0; q < 3; q++)
        pr[q] = make_float4(hr[q*4], hr[q*4+1], hr[q*4+2], hr[q*4+3]);
}

// h2 = agg2*deg_inv + hr; pool[batch[n]] += h2 (fp32 REDs); count nodes/graph.
__global__ __launch_bounds__(256) void combine2_pool(const long long* __restrict__ batch) {
    int n = blockIdx.x * blockDim.x + threadIdx.x;
    if (n >= NN) return;
    float di = g_deginv[n];
    uint4 a0 = *((const uint4*)g_agg2h + n * 2);
    uint2 a1 = *(const uint2*)((const uint4*)g_agg2h + n * 2 + 1);
    float ag[10];
    {
        float2 p;
        p = __half22float2(*(__half2*)&a0.x); ag[0] = p.x; ag[1] = p.y;
        p = __half22float2(*(__half2*)&a0.y); ag[2] = p.x; ag[3] = p.y;
        p = __half22float2(*(__half2*)&a0.z); ag[4] = p.x; ag[5] = p.y;
        p = __half22float2(*(__half2*)&a0.w); ag[6] = p.x; ag[7] = p.y;
        p = __half22float2(*(__half2*)&a1.x); ag[8] = p.x; ag[9] = p.y;
    }
    const float* hr = (const float*)g_hr + n * PD;
    float h2[12];
#pragma unroll
    for (int d = 0; d < 10; d++) h2[d] = ag[d] * di + hr[d];
    h2[10] = h2[11] = 0.f;
    int b = g_b32 ? ((const int*)batch)[n] : (int)batch[n];
    float4* pp = &g_pool[b * 3];
#pragma unroll
    for (int q = 0; q < 3; q++)
        red4f(&pp[q], make_float4(h2[q*4], h2[q*4+1], h2[q*4+2], h2[q*4+3]));
    atomicAdd(&g_cnt[b], 1);
}

__global__ void final_out(const float* __restrict__ Wfc, float* __restrict__ out) {
    int g = blockIdx.x * blockDim.x + threadIdx.x;
    if (g >= NG) return;
    float c = fmaxf((float)g_cnt[g], 1.0f);
    const float* p = (const float*)g_pool + g * PD;
    float z = 0.f;
#pragma unroll
    for (int d = 0; d < 10; d++) z += p[d] * Wfc[d];
    z /= c;
    out[g] = 1.0f / (1.0f + expf(-z));
}

// ---------------- launch ----------------
extern "C" void kernel_launch(void* const* d_in, const int* in_sizes, int n_in,
                              void* d_out, int out_size) {
    const float *x = 0, *W1l = 0, *W1r = 0, *W2l = 0, *W2r = 0, *Wfc = 0;
    const long long *ei = 0, *batch = 0;
    for (int i = 0; i < n_in; i++) {
        int sz = in_sizes[i];
        if (sz == NN * NF)        x = (const float*)d_in[i];
        else if (sz == DIM * NF)  { if (!W1l) W1l = (const float*)d_in[i]; else W1r = (const float*)d_in[i]; }
        else if (sz == DIM * DIM) { if (!W2l) W2l = (const float*)d_in[i]; else W2r = (const float*)d_in[i]; }
        else if (sz == DIM)       Wfc = (const float*)d_in[i];
        else if (sz == 2 * NE)    ei = (const long long*)d_in[i];
        else if (sz == NN)        batch = (const long long*)d_in[i];
    }
    float* out = (float*)d_out;

    const int TB = 256;
    init_k<<<512, TB>>>(ei, batch);
    gemv1<<<(NN + 63) / 64, TB>>>(x, W1l, W1r);
    edge_agg<0><<<(NE + TB - 1) / TB, TB>>>(ei);
    combine1<<<(NN + TB - 1) / TB, TB>>>(W2l, W2r);
    edge_agg<1><<<(NE + TB - 1) / TB, TB>>>(ei);
    combine2_pool<<<(NN + TB - 1) / TB, TB>>>(batch);
    final_out<<<(NG + TB - 1) / TB, TB>>>(Wfc, out);
}

// round 9
// speedup vs baseline: 2.6895x; 1.0771x over previous
#include <cuda_runtime.h>
#include <cuda_fp16.h>
#include <math.h>

#define NN 50000
#define NF 128
#define DIM 10
#define NE 1600000
#define NG 1000
#define PD 12            // fp32 padded stride for xr

// ---------------- scratch ----------------
__device__ int2   g_edge[NE];       // (src, dst) packed in pass 0, reused pass 1
__device__ int    g_deg[NN];
__device__ float  g_deginv[NN];
__device__ float4 g_xlh[NN * 2];    // xl rows fp16: 16 halfs (10 used, pads 0)
__device__ float4 g_agg1h[NN * 2];  // fp16 accumulators (layer 1)
__device__ float4 g_xr[NN * 3];     // fp32
__device__ float  g_t[NN];          // u . h  (layer-2 edge payload, scalar)
__device__ float  g_w[NN];          // v . h  (layer-2 self term, scalar)
__device__ float  g_acc2[NN];       // fp32 scalar accumulator (layer 2)
__device__ float  g_poolz[NG];      // scalar pool
__device__ int    g_cnt[NG];
__device__ float  g_u[DIM], g_v[DIM];
__device__ int    g_ei32;
__device__ int    g_b32;

__device__ __forceinline__ void redf(float* p, float v) {
    asm volatile("red.global.add.f32 [%0], %1;" :: "l"(p), "f"(v) : "memory");
}
__device__ __forceinline__ void redh8(void* p, uint4 v) {      // 8 halfs, 16B
    asm volatile("red.global.add.noftz.v4.f16x2 [%0], {%1,%2,%3,%4};"
                 :: "l"(p), "r"(v.x), "r"(v.y), "r"(v.z), "r"(v.w) : "memory");
}
__device__ __forceinline__ void redh2(void* p, unsigned v) {   // 2 halfs, 4B
    asm volatile("red.global.add.noftz.f16x2 [%0], %1;"
                 :: "l"(p), "r"(v) : "memory");
}

// ---------------- kernels ----------------
// Zero accumulators; thread 0 detects dtypes; first 10 threads build u,v.
__global__ void init_k(const long long* ei, const long long* batch,
                       const float* W2l, const float* W2r, const float* Wfc) {
    int i = blockIdx.x * blockDim.x + threadIdx.x;
    int stride = gridDim.x * blockDim.x;
    float4 z = make_float4(0.f, 0.f, 0.f, 0.f);
    for (int j = i; j < NN * 2; j += stride) { g_agg1h[j] = z; g_xlh[j] = z; }
    for (int j = i; j < NN; j += stride) { g_deg[j] = 0; g_acc2[j] = 0.f; }
    for (int j = i; j < NG; j += stride) { g_poolz[j] = 0.f; g_cnt[j] = 0; }
    if (i < 10) {   // u_j = sum_d Wfc[d]*W2l[d][j]; v_j likewise with W2r
        float u = 0.f, v = 0.f;
#pragma unroll
        for (int d = 0; d < 10; d++) {
            float f = Wfc[d];
            u += f * W2l[d * 10 + i];
            v += f * W2r[d * 10 + i];
        }
        g_u[i] = u; g_v[i] = v;
    }
    if (i == 0) {
        int f = 0;
        for (int k = 0; k < 64; k++) {
            long long v = ei[k];
            if (v < 0 || v >= NN) f = 1;
        }
        g_ei32 = f;
        int fb = 0;
        for (int k = 0; k < 64; k++) {
            long long v = batch[12000 + k];
            if (v < 0 || v >= NG) fb = 1;
        }
        g_b32 = fb;
    }
}

// Fused GEMV: xl = x@W1l^T (fp16 into g_xlh), xr = x@W1r^T (fp32).
__global__ __launch_bounds__(256) void gemv1(const float* __restrict__ x,
                                             const float* __restrict__ W1l,
                                             const float* __restrict__ W1r) {
    __shared__ __align__(16) float sW[20 * 128];
    __shared__ __align__(16) float sX[64 * 132];
    int t = threadIdx.x;
    for (int i = t; i < 20 * 128; i += 256) {
        int d = i >> 7, k = i & 127;
        sW[i] = (d < 10) ? W1l[d * 128 + k] : W1r[(d - 10) * 128 + k];
    }
    int n0 = blockIdx.x * 64;
    for (int i = t; i < 64 * 32; i += 256) {
        int n = i >> 5, k4 = i & 31;
        int node = n0 + n;
        float4 v = (node < NN) ? ((const float4*)x)[node * 32 + k4]
                               : make_float4(0.f, 0.f, 0.f, 0.f);
        *(float4*)&sX[n * 132 + k4 * 4] = v;
    }
    __syncthreads();
    int n = t & 63, g = t >> 6;
    int node = n0 + n;
    float acc[5] = {0.f, 0.f, 0.f, 0.f, 0.f};
    const float4* xr4 = (const float4*)&sX[n * 132];
    const float4* w4  = (const float4*)sW;
#pragma unroll
    for (int k4 = 0; k4 < 32; k4++) {
        float4 xv = xr4[k4];
#pragma unroll
        for (int j = 0; j < 5; j++) {
            float4 w = w4[(g * 5 + j) * 32 + k4];
            acc[j] += xv.x * w.x + xv.y * w.y + xv.z * w.z + xv.w * w.w;
        }
    }
    if (node < NN) {
        __half* xlh = (__half*)g_xlh;
#pragma unroll
        for (int j = 0; j < 5; j++) {
            int d = g * 5 + j;
            if (d < 10) xlh[node * 16 + d] = __float2half(acc[j]);
            else        ((float*)g_xr)[node * PD + (d - 10)] = acc[j];
        }
    }
}

// Layer-1 edge pass: read edge_index, pack g_edge, count deg,
// RED xl(fp16) into agg1h: one 16B vector RED + one 4B scalar RED.
__global__ __launch_bounds__(256) void edge_agg1(const long long* __restrict__ ei) {
    int e = blockIdx.x * blockDim.x + threadIdx.x;
    if (e >= NE) return;
    int s, d;
    if (g_ei32) {
        const int* e32 = (const int*)ei;
        s = e32[e]; d = e32[NE + e];
    } else {
        s = (int)ei[e]; d = (int)ei[NE + e];
    }
    g_edge[e] = make_int2(s, d);
    atomicAdd(&g_deg[d], 1);
    uint4 u0 = *((const uint4*)g_xlh + s * 2);            // dims 0-7
    unsigned t89 = ((const unsigned*)g_xlh)[s * 8 + 4];   // dims 8-9
    char* row = (char*)g_agg1h + (size_t)d * 32;
    redh8(row, u0);
    redh2(row + 16, t89);
}

// h = relu(agg1*deg_inv + xr); t = u.h; w = v.h; store deginv.
__global__ __launch_bounds__(256) void combine1() {
    __shared__ float su[10], sv[10];
    int t = threadIdx.x;
    if (t < 10) { su[t] = g_u[t]; sv[t] = g_v[t]; }
    __syncthreads();
    int n = blockIdx.x * blockDim.x + t;
    if (n >= NN) return;
    float di = 1.0f / fmaxf((float)g_deg[n], 1.0f);
    g_deginv[n] = di;
    uint4 a0 = *((const uint4*)g_agg1h + n * 2);
    unsigned a1 = ((const unsigned*)g_agg1h)[n * 8 + 4];
    float ag[10];
    {
        float2 p;
        p = __half22float2(*(__half2*)&a0.x); ag[0] = p.x; ag[1] = p.y;
        p = __half22float2(*(__half2*)&a0.y); ag[2] = p.x; ag[3] = p.y;
        p = __half22float2(*(__half2*)&a0.z); ag[4] = p.x; ag[5] = p.y;
        p = __half22float2(*(__half2*)&a0.w); ag[6] = p.x; ag[7] = p.y;
        p = __half22float2(*(__half2*)&a1);   ag[8] = p.x; ag[9] = p.y;
    }
    const float* xr = (const float*)g_xr + n * PD;
    float tv = 0.f, wv = 0.f;
#pragma unroll
    for (int d = 0; d < 10; d++) {
        float h = fmaxf(ag[d] * di + xr[d], 0.f);
        tv += su[d] * h;
        wv += sv[d] * h;
    }
    g_t[n] = tv;
    g_w[n] = wv;
}

// Layer-2 edge pass: ONE scalar fp32 RED per edge.
__global__ __launch_bounds__(256) void edge_agg2() {
    int e = blockIdx.x * blockDim.x + threadIdx.x;
    if (e >= NE) return;
    int2 sd = g_edge[e];
    redf(&g_acc2[sd.y], g_t[sd.x]);
}

// val = deg_inv*acc2 + w; pool[batch] += val; count nodes.
__global__ __launch_bounds__(256) void combine2_pool(const long long* __restrict__ batch) {
    int n = blockIdx.x * blockDim.x + threadIdx.x;
    if (n >= NN) return;
    float val = g_deginv[n] * g_acc2[n] + g_w[n];
    int b = g_b32 ? ((const int*)batch)[n] : (int)batch[n];
    redf(&g_poolz[b], val);
    atomicAdd(&g_cnt[b], 1);
}

__global__ void final_out(float* __restrict__ out) {
    int g = blockIdx.x * blockDim.x + threadIdx.x;
    if (g >= NG) return;
    float c = fmaxf((float)g_cnt[g], 1.0f);
    float z = g_poolz[g] / c;
    out[g] = 1.0f / (1.0f + expf(-z));
}

// ---------------- launch ----------------
extern "C" void kernel_launch(void* const* d_in, const int* in_sizes, int n_in,
                              void* d_out, int out_size) {
    const float *x = 0, *W1l = 0, *W1r = 0, *W2l = 0, *W2r = 0, *Wfc = 0;
    const long long *ei = 0, *batch = 0;
    for (int i = 0; i < n_in; i++) {
        int sz = in_sizes[i];
        if (sz == NN * NF)        x = (const float*)d_in[i];
        else if (sz == DIM * NF)  { if (!W1l) W1l = (const float*)d_in[i]; else W1r = (const float*)d_in[i]; }
        else if (sz == DIM * DIM) { if (!W2l) W2l = (const float*)d_in[i]; else W2r = (const float*)d_in[i]; }
        else if (sz == DIM)       Wfc = (const float*)d_in[i];
        else if (sz == 2 * NE)    ei = (const long long*)d_in[i];
        else if (sz == NN)        batch = (const long long*)d_in[i];
    }
    float* out = (float*)d_out;

    const int TB = 256;
    init_k<<<512, TB>>>(ei, batch, W2l, W2r, Wfc);
    gemv1<<<(NN + 63) / 64, TB>>>(x, W1l, W1r);
    edge_agg1<<<(NE + TB - 1) / TB, TB>>>(ei);
    combine1<<<(NN + TB - 1) / TB, TB>>>();
    edge_agg2<<<(NE + TB - 1) / TB, TB>>>();
    combine2_pool<<<(NN + TB - 1) / TB, TB>>>(batch);
    final_out<<<(NG + TB - 1) / TB, TB>>>(out);
}

// round 10
// speedup vs baseline: 2.8986x; 1.0778x over previous
#include <cuda_runtime.h>
#include <cuda_fp16.h>
#include <math.h>

#define NN 50000
#define NF 128
#define DIM 10
#define NE 1600000
#define NG 1000
#define PD 12            // fp32 padded stride for xr

// ---------------- scratch ----------------
__device__ int2   g_edge[NE];       // (src, dst) packed in pass 0, reused pass 1
__device__ float  g_deginv[NN];
__device__ float4 g_xlh[NN * 2];    // xl rows fp16: 16 halfs (10 vals, [10]=1.0 count, [11]=0)
__device__ float4 g_agg1h[NN * 2];  // fp16 accumulators; lane 10 accumulates degree
__device__ float4 g_xr[NN * 3];     // fp32
__device__ float  g_t[NN];          // u . h  (layer-2 edge payload, scalar)
__device__ float  g_w[NN];          // v . h  (layer-2 self term, scalar)
__device__ float  g_acc2[NN];       // fp32 scalar accumulator (layer 2)
__device__ float  g_poolz[NG];      // scalar pool
__device__ int    g_cnt[NG];
__device__ float  g_u[DIM], g_v[DIM];
__device__ int    g_ei32;
__device__ int    g_b32;

__device__ __forceinline__ void redf(float* p, float v) {
    asm volatile("red.global.add.f32 [%0], %1;" :: "l"(p), "f"(v) : "memory");
}
__device__ __forceinline__ void redh8(void* p, uint4 v) {      // 8 halfs, 16B
    asm volatile("red.global.add.noftz.v4.f16x2 [%0], {%1,%2,%3,%4};"
                 :: "l"(p), "r"(v.x), "r"(v.y), "r"(v.z), "r"(v.w) : "memory");
}
__device__ __forceinline__ void redh4(void* p, uint2 v) {      // 4 halfs, 8B
    asm volatile("red.global.add.noftz.v2.f16x2 [%0], {%1,%2};"
                 :: "l"(p), "r"(v.x), "r"(v.y) : "memory");
}

// ---------------- kernels ----------------
// Zero accumulators; thread 0 detects dtypes; first 10 threads build u,v.
__global__ void init_k(const long long* ei, const long long* batch,
                       const float* W2l, const float* W2r, const float* Wfc) {
    int i = blockIdx.x * blockDim.x + threadIdx.x;
    int stride = gridDim.x * blockDim.x;
    float4 z = make_float4(0.f, 0.f, 0.f, 0.f);
    for (int j = i; j < NN * 2; j += stride) g_agg1h[j] = z;
    for (int j = i; j < NN; j += stride) g_acc2[j] = 0.f;
    for (int j = i; j < NG; j += stride) { g_poolz[j] = 0.f; g_cnt[j] = 0; }
    if (i < 10) {   // u_j = sum_d Wfc[d]*W2l[d][j]; v_j likewise with W2r
        float u = 0.f, v = 0.f;
#pragma unroll
        for (int d = 0; d < 10; d++) {
            float f = Wfc[d];
            u += f * W2l[d * 10 + i];
            v += f * W2r[d * 10 + i];
        }
        g_u[i] = u; g_v[i] = v;
    }
    if (i == 0) {
        int f = 0;
        for (int k = 0; k < 64; k++) {
            long long v = ei[k];
            if (v < 0 || v >= NN) f = 1;
        }
        g_ei32 = f;
        int fb = 0;
        for (int k = 0; k < 64; k++) {
            long long v = batch[12000 + k];
            if (v < 0 || v >= NG) fb = 1;
        }
        g_b32 = fb;
    }
}

// Fused GEMV: xl = x@W1l^T (fp16 into g_xlh, +count lane), xr = x@W1r^T (fp32).
__global__ __launch_bounds__(256) void gemv1(const float* __restrict__ x,
                                             const float* __restrict__ W1l,
                                             const float* __restrict__ W1r) {
    __shared__ __align__(16) float sW[20 * 128];
    __shared__ __align__(16) float sX[64 * 132];
    int t = threadIdx.x;
    for (int i = t; i < 20 * 128; i += 256) {
        int d = i >> 7, k = i & 127;
        sW[i] = (d < 10) ? W1l[d * 128 + k] : W1r[(d - 10) * 128 + k];
    }
    int n0 = blockIdx.x * 64;
    for (int i = t; i < 64 * 32; i += 256) {
        int n = i >> 5, k4 = i & 31;
        int node = n0 + n;
        float4 v = (node < NN) ? ((const float4*)x)[node * 32 + k4]
                               : make_float4(0.f, 0.f, 0.f, 0.f);
        *(float4*)&sX[n * 132 + k4 * 4] = v;
    }
    __syncthreads();
    int n = t & 63, g = t >> 6;
    int node = n0 + n;
    float acc[5] = {0.f, 0.f, 0.f, 0.f, 0.f};
    const float4* xr4 = (const float4*)&sX[n * 132];
    const float4* w4  = (const float4*)sW;
#pragma unroll
    for (int k4 = 0; k4 < 32; k4++) {
        float4 xv = xr4[k4];
#pragma unroll
        for (int j = 0; j < 5; j++) {
            float4 w = w4[(g * 5 + j) * 32 + k4];
            acc[j] += xv.x * w.x + xv.y * w.y + xv.z * w.z + xv.w * w.w;
        }
    }
    if (node < NN) {
        __half* xlh = (__half*)g_xlh;
#pragma unroll
        for (int j = 0; j < 5; j++) {
            int d = g * 5 + j;
            if (d < 10) xlh[node * 16 + d] = __float2half(acc[j]);
            else        ((float*)g_xr)[node * PD + (d - 10)] = acc[j];
        }
        if (g == 1) {   // count lane + zero pad (lanes 10,11)
            *(__half2*)&xlh[node * 16 + 10] = __halves2half2(__float2half(1.0f), __float2half(0.0f));
        }
    }
}

// Layer-1 edge pass: read edge_index, pack g_edge, RED xl(fp16) into agg1h.
// 2 RMW transactions/edge: 16B (dims 0-7) + 8B (dims 8-9 + count + pad).
__global__ __launch_bounds__(256) void edge_agg1(const long long* __restrict__ ei) {
    int e = blockIdx.x * blockDim.x + threadIdx.x;
    if (e >= NE) return;
    int s, d;
    if (g_ei32) {
        const int* e32 = (const int*)ei;
        s = e32[e]; d = e32[NE + e];
    } else {
        s = (int)ei[e]; d = (int)ei[NE + e];
    }
    g_edge[e] = make_int2(s, d);
    uint4 u0 = *((const uint4*)g_xlh + s * 2);            // dims 0-7
    uint2 u1 = ((const uint2*)g_xlh)[s * 4 + 2];          // dims 8,9,count,0
    char* row = (char*)g_agg1h + (size_t)d * 32;
    redh8(row, u0);
    redh4(row + 16, u1);
}

// deg from count lane; h = relu(agg1/deg + xr); t = u.h; w = v.h.
__global__ __launch_bounds__(256) void combine1() {
    __shared__ float su[10], sv[10];
    int t = threadIdx.x;
    if (t < 10) { su[t] = g_u[t]; sv[t] = g_v[t]; }
    __syncthreads();
    int n = blockIdx.x * blockDim.x + t;
    if (n >= NN) return;
    uint4 a0 = *((const uint4*)g_agg1h + n * 2);
    uint2 a1 = ((const uint2*)g_agg1h)[n * 4 + 2];
    float ag[10];
    float2 p;
    p = __half22float2(*(__half2*)&a0.x); ag[0] = p.x; ag[1] = p.y;
    p = __half22float2(*(__half2*)&a0.y); ag[2] = p.x; ag[3] = p.y;
    p = __half22float2(*(__half2*)&a0.z); ag[4] = p.x; ag[5] = p.y;
    p = __half22float2(*(__half2*)&a0.w); ag[6] = p.x; ag[7] = p.y;
    p = __half22float2(*(__half2*)&a1.x); ag[8] = p.x; ag[9] = p.y;
    p = __half22float2(*(__half2*)&a1.y);          // p.x = degree (fp16-exact int)
    float di = 1.0f / fmaxf(p.x, 1.0f);
    g_deginv[n] = di;
    const float4* xr4 = (const float4*)((const float*)g_xr + n * PD);
    float4 x0 = xr4[0], x1 = xr4[1], x2 = xr4[2];
    float xr[10] = {x0.x, x0.y, x0.z, x0.w, x1.x, x1.y, x1.z, x1.w, x2.x, x2.y};
    float tv = 0.f, wv = 0.f;
#pragma unroll
    for (int d = 0; d < 10; d++) {
        float h = fmaxf(ag[d] * di + xr[d], 0.f);
        tv += su[d] * h;
        wv += sv[d] * h;
    }
    g_t[n] = tv;
    g_w[n] = wv;
}

// Layer-2 edge pass: ONE scalar fp32 RED per edge; 2 edges/thread.
__global__ __launch_bounds__(256) void edge_agg2() {
    int t = blockIdx.x * blockDim.x + threadIdx.x;
    int e0 = t * 2;
    if (e0 >= NE) return;
    int4 p = *(const int4*)&g_edge[e0];     // two (src,dst) pairs
    redf(&g_acc2[p.y], g_t[p.x]);
    redf(&g_acc2[p.w], g_t[p.z]);           // NE is even
}

// val = deg_inv*acc2 + w; pool[batch] += val; count nodes.
__global__ __launch_bounds__(256) void combine2_pool(const long long* __restrict__ batch) {
    int n = blockIdx.x * blockDim.x + threadIdx.x;
    if (n >= NN) return;
    float val = g_deginv[n] * g_acc2[n] + g_w[n];
    int b = g_b32 ? ((const int*)batch)[n] : (int)batch[n];
    redf(&g_poolz[b], val);
    atomicAdd(&g_cnt[b], 1);
}

__global__ void final_out(float* __restrict__ out) {
    int g = blockIdx.x * blockDim.x + threadIdx.x;
    if (g >= NG) return;
    float c = fmaxf((float)g_cnt[g], 1.0f);
    float z = g_poolz[g] / c;
    out[g] = 1.0f / (1.0f + expf(-z));
}

// ---------------- launch ----------------
extern "C" void kernel_launch(void* const* d_in, const int* in_sizes, int n_in,
                              void* d_out, int out_size) {
    const float *x = 0, *W1l = 0, *W1r = 0, *W2l = 0, *W2r = 0, *Wfc = 0;
    const long long *ei = 0, *batch = 0;
    for (int i = 0; i < n_in; i++) {
        int sz = in_sizes[i];
        if (sz == NN * NF)        x = (const float*)d_in[i];
        else if (sz == DIM * NF)  { if (!W1l) W1l = (const float*)d_in[i]; else W1r = (const float*)d_in[i]; }
        else if (sz == DIM * DIM) { if (!W2l) W2l = (const float*)d_in[i]; else W2r = (const float*)d_in[i]; }
        else if (sz == DIM)       Wfc = (const float*)d_in[i];
        else if (sz == 2 * NE)    ei = (const long long*)d_in[i];
        else if (sz == NN)        batch = (const long long*)d_in[i];
    }
    float* out = (float*)d_out;

    const int TB = 256;
    init_k<<<512, TB>>>(ei, batch, W2l, W2r, Wfc);
    gemv1<<<(NN + 63) / 64, TB>>>(x, W1l, W1r);
    edge_agg1<<<(NE + TB - 1) / TB, TB>>>(ei);
    combine1<<<(NN + TB - 1) / TB, TB>>>();
    edge_agg2<<<(NE / 2 + TB - 1) / TB, TB>>>();
    combine2_pool<<<(NN + TB - 1) / TB, TB>>>(batch);
    final_out<<<(NG + TB - 1) / TB, TB>>>(out);
}

// round 12
// speedup vs baseline: 2.9081x; 1.0033x over previous
#include <cuda_runtime.h>
#include <cuda_fp16.h>
#include <math.h>

#define NN 50000
#define NF 128
#define DIM 10
#define NE 1600000
#define NG 1000
#define PD 12            // fp32 padded stride for xr

// ---------------- scratch ----------------
__device__ int2   g_edge[NE];       // (src, dst) packed in pass 0, reused pass 1
__device__ float  g_deginv[NN];
__device__ float4 g_xlh[NN * 2];    // xl rows fp16: 16 halfs (10 vals, [10]=1.0 count, [11]=0)
__device__ float4 g_agg1h[NN * 2];  // fp16 accumulators; lane 10 accumulates degree
__device__ float4 g_xr[NN * 3];     // fp32
__device__ float  g_t[NN];          // u . h  (layer-2 edge payload, scalar)
__device__ float  g_w[NN];          // v . h  (layer-2 self term, scalar)
__device__ float  g_acc2[NN];       // fp32 scalar accumulator (layer 2)
__device__ float  g_poolz[NG];      // scalar pool
__device__ int    g_cnt[NG];
__device__ float  g_u[DIM], g_v[DIM];
__device__ int    g_done;           // last-block ticket (reset every call)
__device__ int    g_ei32;
__device__ int    g_b32;

__device__ __forceinline__ void redf(float* p, float v) {
    asm volatile("red.global.add.f32 [%0], %1;" :: "l"(p), "f"(v) : "memory");
}
__device__ __forceinline__ void redh8(void* p, uint4 v) {      // 8 halfs, 16B
    asm volatile("red.global.add.noftz.v4.f16x2 [%0], {%1,%2,%3,%4};"
                 :: "l"(p), "r"(v.x), "r"(v.y), "r"(v.z), "r"(v.w) : "memory");
}
__device__ __forceinline__ void redh4(void* p, uint2 v) {      // 4 halfs, 8B
    asm volatile("red.global.add.noftz.v2.f16x2 [%0], {%1,%2};"
                 :: "l"(p), "r"(v.x), "r"(v.y) : "memory");
}

// ---------------- kernels ----------------
// ONE block: dtype detect, u/v build, zero pool/cnt/done.
__global__ void init_small(const long long* ei, const long long* batch,
                           const float* W2l, const float* W2r, const float* Wfc) {
    int i = threadIdx.x;
    for (int j = i; j < NG; j += 256) { g_poolz[j] = 0.f; g_cnt[j] = 0; }
    if (i == 255) g_done = 0;
    if (i < 10) {   // u_j = sum_d Wfc[d]*W2l[d][j]; v_j likewise with W2r
        float u = 0.f, v = 0.f;
#pragma unroll
        for (int d = 0; d < 10; d++) {
            float f = Wfc[d];
            u += f * W2l[d * 10 + i];
            v += f * W2r[d * 10 + i];
        }
        g_u[i] = u; g_v[i] = v;
    }
    if (i == 0) {
        int f = 0;
        for (int k = 0; k < 64; k++) {
            long long v = ei[k];
            if (v < 0 || v >= NN) f = 1;
        }
        g_ei32 = f;
        int fb = 0;
        for (int k = 0; k < 64; k++) {
            long long v = batch[12000 + k];
            if (v < 0 || v >= NG) fb = 1;
        }
        g_b32 = fb;
    }
}

// Fused GEMV: xl = x@W1l^T (fp16 into g_xlh, +count lane), xr = x@W1r^T (fp32).
// Also zeroes this block's slice of g_agg1h / g_acc2 (no separate init pass).
__global__ __launch_bounds__(256) void gemv1(const float* __restrict__ x,
                                             const float* __restrict__ W1l,
                                             const float* __restrict__ W1r) {
    __shared__ __align__(16) float sW[20 * 128];
    __shared__ __align__(16) float sX[64 * 132];
    int t = threadIdx.x;
    int n0 = blockIdx.x * 64;
    // zero accumulator slices for this block's nodes
    {
        float4 z = make_float4(0.f, 0.f, 0.f, 0.f);
        for (int i = t; i < 128; i += 256) {
            int node = n0 + (i >> 1);
            if (node < NN) g_agg1h[node * 2 + (i & 1)] = z;
        }
        for (int i = t; i < 64; i += 256) {
            int node = n0 + i;
            if (node < NN) g_acc2[node] = 0.f;
        }
    }
    for (int i = t; i < 20 * 128; i += 256) {
        int d = i >> 7, k = i & 127;
        sW[i] = (d < 10) ? W1l[d * 128 + k] : W1r[(d - 10) * 128 + k];
    }
    for (int i = t; i < 64 * 32; i += 256) {
        int n = i >> 5, k4 = i & 31;
        int node = n0 + n;
        float4 v = (node < NN) ? ((const float4*)x)[node * 32 + k4]
                               : make_float4(0.f, 0.f, 0.f, 0.f);
        *(float4*)&sX[n * 132 + k4 * 4] = v;
    }
    __syncthreads();
    int n = t & 63, g = t >> 6;
    int node = n0 + n;
    float acc[5] = {0.f, 0.f, 0.f, 0.f, 0.f};
    const float4* xr4 = (const float4*)&sX[n * 132];
    const float4* w4  = (const float4*)sW;
#pragma unroll
    for (int k4 = 0; k4 < 32; k4++) {
        float4 xv = xr4[k4];
#pragma unroll
        for (int j = 0; j < 5; j++) {
            float4 w = w4[(g * 5 + j) * 32 + k4];
            acc[j] += xv.x * w.x + xv.y * w.y + xv.z * w.z + xv.w * w.w;
        }
    }
    if (node < NN) {
        __half* xlh = (__half*)g_xlh;
#pragma unroll
        for (int j = 0; j < 5; j++) {
            int d = g * 5 + j;
            if (d < 10) xlh[node * 16 + d] = __float2half(acc[j]);
            else        ((float*)g_xr)[node * PD + (d - 10)] = acc[j];
        }
        if (g == 1) {   // count lane + zero pad (lanes 10,11)
            *(__half2*)&xlh[node * 16 + 10] = __halves2half2(__float2half(1.0f), __float2half(0.0f));
        }
    }
}

// Layer-1 edge pass, 2 edges/thread: vector ei loads, int4 pack store,
// 2 RMW transactions per edge (16B dims0-7 + 8B dims8-9/count/pad).
__global__ __launch_bounds__(256) void edge_agg1(const long long* __restrict__ ei) {
    int t = blockIdx.x * blockDim.x + threadIdx.x;
    int e0 = t * 2;
    if (e0 >= NE) return;          // NE even: always full pairs
    int s0, s1, d0, d1;
    if (g_ei32) {
        const int* e32 = (const int*)ei;
        int2 ss = ((const int2*)e32)[t];
        int2 dd = ((const int2*)(e32 + NE))[t];
        s0 = ss.x; s1 = ss.y; d0 = dd.x; d1 = dd.y;
    } else {
        longlong2 ss = ((const longlong2*)ei)[t];
        longlong2 dd = ((const longlong2*)(ei + NE))[t];
        s0 = (int)ss.x; s1 = (int)ss.y; d0 = (int)dd.x; d1 = (int)dd.y;
    }
    *(int4*)&g_edge[e0] = make_int4(s0, d0, s1, d1);
    uint4 u0 = *((const uint4*)g_xlh + s0 * 2);
    uint2 u1 = ((const uint2*)g_xlh)[s0 * 4 + 2];
    uint4 v0 = *((const uint4*)g_xlh + s1 * 2);
    uint2 v1 = ((const uint2*)g_xlh)[s1 * 4 + 2];
    char* r0 = (char*)g_agg1h + (size_t)d0 * 32;
    char* r1 = (char*)g_agg1h + (size_t)d1 * 32;
    redh8(r0, u0);
    redh4(r0 + 16, u1);
    redh8(r1, v0);
    redh4(r1 + 16, v1);
}

// deg from count lane; h = relu(agg1/deg + xr); t = u.h; w = v.h.
__global__ __launch_bounds__(256) void combine1() {
    __shared__ float su[10], sv[10];
    int t = threadIdx.x;
    if (t < 10) { su[t] = g_u[t]; sv[t] = g_v[t]; }
    __syncthreads();
    int n = blockIdx.x * blockDim.x + t;
    if (n >= NN) return;
    uint4 a0 = *((const uint4*)g_agg1h + n * 2);
    uint2 a1 = ((const uint2*)g_agg1h)[n * 4 + 2];
    float ag[10];
    float2 p;
    p = __half22float2(*(__half2*)&a0.x); ag[0] = p.x; ag[1] = p.y;
    p = __half22float2(*(__half2*)&a0.y); ag[2] = p.x; ag[3] = p.y;
    p = __half22float2(*(__half2*)&a0.z); ag[4] = p.x; ag[5] = p.y;
    p = __half22float2(*(__half2*)&a0.w); ag[6] = p.x; ag[7] = p.y;
    p = __half22float2(*(__half2*)&a1.x); ag[8] = p.x; ag[9] = p.y;
    p = __half22float2(*(__half2*)&a1.y);          // p.x = degree (fp16-exact int)
    float di = 1.0f / fmaxf(p.x, 1.0f);
    g_deginv[n] = di;
    const float4* xr4 = (const float4*)((const float*)g_xr + n * PD);
    float4 x0 = xr4[0], x1 = xr4[1], x2 = xr4[2];
    float xr[10] = {x0.x, x0.y, x0.z, x0.w, x1.x, x1.y, x1.z, x1.w, x2.x, x2.y};
    float tv = 0.f, wv = 0.f;
#pragma unroll
    for (int d = 0; d < 10; d++) {
        float h = fmaxf(ag[d] * di + xr[d], 0.f);
        tv += su[d] * h;
        wv += sv[d] * h;
    }
    g_t[n] = tv;
    g_w[n] = wv;
}

// Layer-2 edge pass: ONE scalar fp32 RED per edge; 4 edges/thread.
__global__ __launch_bounds__(256) void edge_agg2() {
    int t = blockIdx.x * blockDim.x + threadIdx.x;
    int e0 = t * 4;
    if (e0 >= NE) return;          // NE % 4 == 0: always full quads
    int4 p = *(const int4*)&g_edge[e0];
    int4 q = *(const int4*)&g_edge[e0 + 2];
    float t0 = g_t[p.x], t1 = g_t[p.z], t2 = g_t[q.x], t3 = g_t[q.z];
    redf(&g_acc2[p.y], t0);
    redf(&g_acc2[p.w], t1);
    redf(&g_acc2[q.y], t2);
    redf(&g_acc2[q.w], t3);
}

// val = deg_inv*acc2 + w; pool[batch] += val; count; last block writes output.
__global__ __launch_bounds__(256) void combine2_pool(const long long* __restrict__ batch,
                                                     float* __restrict__ out) {
    int n = blockIdx.x * blockDim.x + threadIdx.x;
    if (n < NN) {
        float val = g_deginv[n] * g_acc2[n] + g_w[n];
        int b = g_b32 ? ((const int*)batch)[n] : (int)batch[n];
        redf(&g_poolz[b], val);
        atomicAdd(&g_cnt[b], 1);
    }
    __threadfence();
    __shared__ int last;
    if (threadIdx.x == 0)
        last = (atomicAdd(&g_done, 1) == (int)gridDim.x - 1);
    __syncthreads();
    if (last) {
        __threadfence();
        for (int g = threadIdx.x; g < NG; g += blockDim.x) {
            float c = fmaxf((float)g_cnt[g], 1.0f);
            float z = g_poolz[g] / c;
            out[g] = 1.0f / (1.0f + expf(-z));
        }
    }
}

// ---------------- launch ----------------
extern "C" void kernel_launch(void* const* d_in, const int* in_sizes, int n_in,
                              void* d_out, int out_size) {
    const float *x = 0, *W1l = 0, *W1r = 0, *W2l = 0, *W2r = 0, *Wfc = 0;
    const long long *ei = 0, *batch = 0;
    for (int i = 0; i < n_in; i++) {
        int sz = in_sizes[i];
        if (sz == NN * NF)        x = (const float*)d_in[i];
        else if (sz == DIM * NF)  { if (!W1l) W1l = (const float*)d_in[i]; else W1r = (const float*)d_in[i]; }
        else if (sz == DIM * DIM) { if (!W2l) W2l = (const float*)d_in[i]; else W2r = (const float*)d_in[i]; }
        else if (sz == DIM)       Wfc = (const float*)d_in[i];
        else if (sz == 2 * NE)    ei = (const long long*)d_in[i];
        else if (sz == NN)        batch = (const long long*)d_in[i];
    }
    float* out = (float*)d_out;

    const int TB = 256;
    init_small<<<1, TB>>>(ei, batch, W2l, W2r, Wfc);
    gemv1<<<(NN + 63) / 64, TB>>>(x, W1l, W1r);
    edge_agg1<<<(NE / 2 + TB - 1) / TB, TB>>>(ei);
    combine1<<<(NN + TB - 1) / TB, TB>>>();
    edge_agg2<<<(NE / 4 + TB - 1) / TB, TB>>>();
    combine2_pool<<<(NN + TB - 1) / TB, TB>>>(batch, out);
}